// round 5
// baseline (speedup 1.0000x reference)
#include <cuda_runtime.h>
#include <cstdint>

// Problem constants: x is (16384, 2048) fp32, angles (2048,) fp32, out (16384, 2048) fp32.
constexpr int NN = 2048;   // row length n
constexpr int T  = 256;    // threads per block
constexpr int E  = 8;      // elements per thread (T*E == NN)
constexpr int R  = 4;      // rows per block

// Precomputed tables (device globals: no dynamic allocation allowed).
__device__ __align__(16) float g_c[NN];
__device__ __align__(16) float g_s[NN];
// Row-independent scan weights (P-side of the affine scan):
__device__ float g_W5[5][T];   // warp suffix-scan jump weights
__device__ float g_Pe[T];      // warp-exclusive product (lanes > lid, same warp)
__device__ float g_PfA[T];     // block-exclusive product (threads > t)
__device__ float g_Pw[8];      // per-warp total products

// Single fused prep: sincos for all angles + every P-side scan constant.
// One block of T threads; each owns E consecutive angles.
__global__ void prep_kernel(const float* __restrict__ ang) {
    __shared__ float sP[T];
    const int t = threadIdx.x, lid = t & 31, w = t >> 5, lo = t * E;

    float ssl[E];
#pragma unroll
    for (int m = 0; m < E; ++m) {
        float s, c;
        sincosf(ang[lo + m], &s, &c);
        g_c[lo + m] = c;
        g_s[lo + m] = s;
        ssl[m] = s;
    }

    float P = 1.f;
#pragma unroll
    for (int m = E - 1; m >= 0; --m) {
        if (lo + m == NN - 1) continue;       // k = N-1 is the seed, not a scan step
        P *= -ssl[m];
    }
    sP[t] = P;
    __syncthreads();

    // Hillis-Steele suffix-scan jump weights (prod_{i=0..d-1} sP[t+i]; 0 past warp end).
    int d = 1;
    for (int di = 0; di < 5; ++di, d <<= 1) {
        float wgt = 0.f;
        if (lid + d < 32) {
            wgt = 1.f;
            for (int i = 0; i < d; ++i) wgt *= sP[t + i];
        }
        g_W5[di][t] = wgt;
    }
    float Pe = 1.f;
    for (int l = lid + 1; l < 32; ++l) Pe *= sP[(w << 5) + l];
    g_Pe[t] = Pe;
    float Pf = Pe;
    for (int t2 = (w + 1) << 5; t2 < T; ++t2) Pf *= sP[t2];
    g_PfA[t] = Pf;
    if (t < 8) {
        float p = 1.f;
        for (int l = 0; l < 32; ++l) p *= sP[(t << 5) + l];
        g_Pw[t] = p;
    }
}

// y_row = G_0 (G_1 (... (G_{N-1} x_row))). First-order affine recurrence on the
// carry; Q-only weighted suffix scan per row (P-side precomputed). Next row's
// loads are issued before this row's barrier (2-deep cross-row MLP).
__global__ void __launch_bounds__(T, 4) givens_kernel(const float* __restrict__ x,
                                                      float* __restrict__ y,
                                                      int rows) {
    __shared__ __align__(16) float wtQ[2][8];   // double-buffered warp Q-totals

    const int t   = threadIdx.x;
    const int lid = t & 31;
    const int w   = t >> 5;
    const int lo  = t * E;
    const long base = (long)blockIdx.x * R;

    // ---- per-block constants into registers ----
    float cc[E], ss[E];
    {
        float4 c0 = reinterpret_cast<const float4*>(g_c + lo)[0];
        float4 c1 = reinterpret_cast<const float4*>(g_c + lo)[1];
        cc[0] = c0.x; cc[1] = c0.y; cc[2] = c0.z; cc[3] = c0.w;
        cc[4] = c1.x; cc[5] = c1.y; cc[6] = c1.z; cc[7] = c1.w;
        float4 s0 = reinterpret_cast<const float4*>(g_s + lo)[0];
        float4 s1 = reinterpret_cast<const float4*>(g_s + lo)[1];
        ss[0] = s0.x; ss[1] = s0.y; ss[2] = s0.z; ss[3] = s0.w;
        ss[4] = s1.x; ss[5] = s1.y; ss[6] = s1.z; ss[7] = s1.w;
    }
    float W[5];
#pragma unroll
    for (int di = 0; di < 5; ++di) W[di] = g_W5[di][t];
    const float Pe = g_Pe[t];
    const float Pf = g_PfA[t];
    const float pw1 = g_Pw[1], pw2 = g_Pw[2], pw3 = g_Pw[3],
                pw4 = g_Pw[4], pw5 = g_Pw[5], pw6 = g_Pw[6];
    const float cN = g_c[NN - 1];
    const float sN = g_s[NN - 1];

    // Warp-head lanes (lane 0 of warps 1..7) rebuild out[lo] locally:
    // out[lo] = s[lo-1]*x[lo-1] + c[lo-1]*prev_lo.
    const bool warp_head = (lid == 0) && (w > 0);
    float cprev = 0.f, sprev = 0.f;
    if (warp_head) { cprev = g_c[lo - 1]; sprev = g_s[lo - 1]; }

    // ---- prologue: loads for row 0 (streaming: each byte touched once) ----
    const float* xr0 = x + base * NN;
    float4 a0 = __ldcs(reinterpret_cast<const float4*>(xr0 + lo));
    float4 a1 = __ldcs(reinterpret_cast<const float4*>(xr0 + lo) + 1);
    float x0  = __ldg(xr0);
    float xn1 = __ldg(xr0 + NN - 1);
    float xprev = warp_head ? __ldg(xr0 + lo - 1) : 0.f;

#pragma unroll 1
    for (int r = 0; r < R; ++r) {
        if (base + r >= rows) break;

        float xv[E];
        xv[0] = a0.x; xv[1] = a0.y; xv[2] = a0.z; xv[3] = a0.w;
        xv[4] = a1.x; xv[5] = a1.y; xv[6] = a1.z; xv[7] = a1.w;
        const float seed = fmaf(cN, xn1, -sN * x0);   // prev_{N-1}
        if (t == 0) xv[0] = fmaf(sN, xn1, cN * x0);   // X_0 = updated x[0]
        const float xpv = xprev;

        // ---- prefetch next row before any scan dependency / barrier ----
        if (r + 1 < R && base + r + 1 < rows) {
            const float* xr2 = x + (base + r + 1) * NN;
            a0 = __ldcs(reinterpret_cast<const float4*>(xr2 + lo));
            a1 = __ldcs(reinterpret_cast<const float4*>(xr2 + lo) + 1);
            x0  = __ldg(xr2);
            xn1 = __ldg(xr2 + NN - 1);
            if (warp_head) xprev = __ldg(xr2 + lo - 1);
        }

        // ---- per-chunk Q composition (f_k(p) = -s_k p + c_k X_k), k descending ----
        float Q = 0.f;
#pragma unroll
        for (int m = E - 1; m >= 0; --m) {
            if (lo + m == NN - 1) continue;           // seed step
            Q = fmaf(-ss[m], Q, cc[m] * xv[m]);
        }

        // ---- Q-only weighted warp suffix scan ----
#pragma unroll
        for (int di = 0, d = 1; di < 5; ++di, d <<= 1) {
            float q2 = __shfl_down_sync(0xffffffffu, Q, d);
            Q = fmaf(W[di], q2, Q);
        }
        float Qe = __shfl_down_sync(0xffffffffu, Q, 1);  // warp-exclusive Q
        if (lid == 31) Qe = 0.f;

        const int buf = r & 1;
        if (lid == 0) wtQ[buf][w] = Q;                   // warp total
        __syncthreads();

        // cross-warp Horner over later warps (w2 = 7 .. w+1), Pw in registers
        float4 qa = *reinterpret_cast<const float4*>(&wtQ[buf][0]);
        float4 qb = *reinterpret_cast<const float4*>(&wtQ[buf][4]);
        float Qp = 0.f;
        if (w < 7) Qp = qb.w;
        if (w < 6) Qp = fmaf(pw6, Qp, qb.z);
        if (w < 5) Qp = fmaf(pw5, Qp, qb.y);
        if (w < 4) Qp = fmaf(pw4, Qp, qb.x);
        if (w < 3) Qp = fmaf(pw3, Qp, qa.w);
        if (w < 2) Qp = fmaf(pw2, Qp, qa.z);
        if (w < 1) Qp = fmaf(pw1, Qp, qa.y);

        float prev = fmaf(Pf, seed, fmaf(Pe, Qp, Qe));   // carry entering chunk top

        // ---- replay in place: xv[m] <- out[lo+m+1]; ends with prev = prev_lo ----
#pragma unroll
        for (int m = E - 1; m >= 0; --m) {
            if (lo + m == NN - 1) { xv[m] = 0.f; continue; }
            const float xm = xv[m];
            xv[m] = fmaf(ss[m], xm, cc[m] * prev);
            prev  = fmaf(-ss[m], prev, cc[m] * xm);
        }

        // out[lo]: lanes 1-31 take previous lane's xv[7]; warp heads recompute;
        // thread 0 has it as prev_0.
        float carry = __shfl_up_sync(0xffffffffu, xv[E - 1], 1);
        if (t == 0)         carry = prev;
        else if (warp_head) carry = fmaf(sprev, xpv, cprev * prev);

        float* yr = y + (base + r) * NN;
        float4 o0, o1;
        o0.x = carry; o0.y = xv[0]; o0.z = xv[1]; o0.w = xv[2];
        o1.x = xv[3]; o1.y = xv[4]; o1.z = xv[5]; o1.w = xv[6];
        __stcs(reinterpret_cast<float4*>(yr + lo), o0);
        __stcs(reinterpret_cast<float4*>(yr + lo) + 1, o1);
    }
}

extern "C" void kernel_launch(void* const* d_in, const int* in_sizes, int n_in,
                              void* d_out, int out_size) {
    const float* x   = (const float*)d_in[0];   // (B, N) fp32
    const float* ang = (const float*)d_in[1];   // (N,)  fp32
    float* y = (float*)d_out;                   // (B, N) fp32

    prep_kernel<<<1, T>>>(ang);

    const int rows   = out_size / NN;           // B = 16384
    const int blocks = (rows + R - 1) / R;      // 4096
    givens_kernel<<<blocks, T>>>(x, y, rows);
}

// round 6
// speedup vs baseline: 1.1106x; 1.1106x over previous
#include <cuda_runtime.h>
#include <cstdint>

// Problem constants: x is (16384, 2048) fp32, angles (2048,) fp32, out (16384, 2048) fp32.
constexpr int NN = 2048;   // row length n
constexpr int T  = 256;    // threads per block
constexpr int E  = 8;      // elements per thread (T*E == NN)
constexpr int R  = 4;      // rows per block

// Precomputed tables (device globals: no dynamic allocation allowed).
__device__ __align__(16) float g_c[NN];
__device__ __align__(16) float g_s[NN];
// Row-independent scan weights (P-side of the affine scan):
__device__ float g_W5[5][T];   // warp suffix-scan jump weights (prod_{i<d} P_{t+i}, 0 past warp end)
__device__ float g_Pe[T];      // warp-exclusive product (lanes > lid, same warp)
__device__ float g_PfA[T];     // block-exclusive product (threads > t)
__device__ float g_Pw[8];      // per-warp total products

// Fused prep, one block: sincos for all angles + all P-side scan constants,
// computed with log-depth scans (no long serial loops).
__global__ void prep_kernel(const float* __restrict__ ang) {
    __shared__ float Slev[T];
    __shared__ float spw[8];
    const int t = threadIdx.x, lid = t & 31, w = t >> 5, lo = t * E;

    float ssl[E];
#pragma unroll
    for (int m = 0; m < E; ++m) {
        float s, c;
        sincosf(ang[lo + m], &s, &c);
        g_c[lo + m] = c;
        g_s[lo + m] = s;
        ssl[m] = s;
    }

    float P = 1.f;
#pragma unroll
    for (int m = E - 1; m >= 0; --m) {
        if (lo + m == NN - 1) continue;       // k = N-1 is the seed, not a scan step
        P *= -ssl[m];
    }

    // W levels by doubling: S_{2h}[t] = S_h[t] * S_h[t+h]   (0 past warp end)
    float S = P;
    g_W5[0][t] = (lid + 1 < 32) ? S : 0.f;
    for (int di = 1; di < 5; ++di) {
        const int d = 1 << di, half = d >> 1;
        __syncthreads();
        Slev[t] = S;
        __syncthreads();
        float part = (lid + half < 32) ? Slev[t + half] : 0.f;
        S *= part;
        g_W5[di][t] = (lid + d < 32) ? S : 0.f;
    }

    // warp inclusive suffix scan of P (prod over lanes >= lid)
    float Pscan = P;
#pragma unroll
    for (int d = 1; d < 32; d <<= 1) {
        float tmp = __shfl_down_sync(0xffffffffu, Pscan, d);
        if (lid + d < 32) Pscan *= tmp;
    }
    float Pe = __shfl_down_sync(0xffffffffu, Pscan, 1);
    if (lid == 31) Pe = 1.f;
    g_Pe[t] = Pe;
    if (lid == 0) spw[w] = Pscan;             // warp total
    __syncthreads();

    float Pf = Pe;
    for (int w2 = w + 1; w2 < 8; ++w2) Pf *= spw[w2];
    g_PfA[t] = Pf;
    if (t < 8) g_Pw[t] = spw[t];
}

// y_row = G_0 (G_1 (... (G_{N-1} x_row))). First-order affine recurrence on the
// carry; Q-only weighted warp suffix scan (P-side precomputed); one barrier/row.
__global__ void __launch_bounds__(T, 5) givens_kernel(const float* __restrict__ x,
                                                      float* __restrict__ y,
                                                      int rows) {
    __shared__ __align__(16) float wtQ[2][8];   // warp Q-totals (double-buffered)
    __shared__ float sxe[2][8];                 // lane-31 x[lo+7] per warp
    __shared__ float sx01[2][2];                // x[0], x[N-1]

    const int t   = threadIdx.x;
    const int lid = t & 31;
    const int w   = t >> 5;
    const int lo  = t * E;
    const long base = (long)blockIdx.x * R;

    // ---- per-block constants into registers ----
    float cc[E], ss[E];
    {
        float4 c0 = reinterpret_cast<const float4*>(g_c + lo)[0];
        float4 c1 = reinterpret_cast<const float4*>(g_c + lo)[1];
        cc[0] = c0.x; cc[1] = c0.y; cc[2] = c0.z; cc[3] = c0.w;
        cc[4] = c1.x; cc[5] = c1.y; cc[6] = c1.z; cc[7] = c1.w;
        float4 s0 = reinterpret_cast<const float4*>(g_s + lo)[0];
        float4 s1 = reinterpret_cast<const float4*>(g_s + lo)[1];
        ss[0] = s0.x; ss[1] = s0.y; ss[2] = s0.z; ss[3] = s0.w;
        ss[4] = s1.x; ss[5] = s1.y; ss[6] = s1.z; ss[7] = s1.w;
    }
    float W[5];
#pragma unroll
    for (int di = 0; di < 5; ++di) W[di] = g_W5[di][t];
    const float Pe = g_Pe[t];
    const float Pf = g_PfA[t];
    const float pw1 = g_Pw[1], pw2 = g_Pw[2], pw3 = g_Pw[3],
                pw4 = g_Pw[4], pw5 = g_Pw[5], pw6 = g_Pw[6];
    const float cN = g_c[NN - 1];
    const float sN = g_s[NN - 1];

    // Warp-head lanes (lane 0 of warps 1..7) rebuild out[lo] locally:
    // out[lo] = s[lo-1]*x[lo-1] + c[lo-1]*prev_lo.
    const bool warp_head = (lid == 0) && (w > 0);
    float cprev = 0.f, sprev = 0.f;
    if (warp_head) { cprev = g_c[lo - 1]; sprev = g_s[lo - 1]; }

#pragma unroll 1
    for (int r = 0; r < R; ++r) {
        if (base + r >= rows) break;
        const float* xr = x + (base + r) * NN;
        const int buf = r & 1;

        float xv[E];
        {
            float4 v0 = __ldcs(reinterpret_cast<const float4*>(xr + lo));
            float4 v1 = __ldcs(reinterpret_cast<const float4*>(xr + lo) + 1);
            xv[0] = v0.x; xv[1] = v0.y; xv[2] = v0.z; xv[3] = v0.w;
            xv[4] = v1.x; xv[5] = v1.y; xv[6] = v1.z; xv[7] = v1.w;
        }
        // Exchange the few boundary values through smem (pre-barrier writes):
        if (lid == 31) sxe[buf][w] = xv[7];   // x[lo+7] -> next warp's head
        if (t == 0)    sx01[buf][0] = xv[0];  // x[0]
        if (t == T-1)  sx01[buf][1] = xv[7];  // x[N-1]

        // ---- per-chunk Q composition (f_k(p) = -s_k p + c_k X_k), k descending ----
        // Thread 0's Q uses the UNcorrected xv[0]; that Q is consumed by nobody
        // (warp-0 total unused, shfl_down never reads lane 0), so this is safe.
        float Q = 0.f;
#pragma unroll
        for (int m = E - 1; m >= 0; --m) {
            if (lo + m == NN - 1) continue;            // seed step
            Q = fmaf(-ss[m], Q, cc[m] * xv[m]);
        }

        // ---- Q-only weighted warp suffix scan ----
#pragma unroll
        for (int di = 0, d = 1; di < 5; ++di, d <<= 1) {
            float q2 = __shfl_down_sync(0xffffffffu, Q, d);
            Q = fmaf(W[di], q2, Q);
        }
        float Qe = __shfl_down_sync(0xffffffffu, Q, 1);   // warp-exclusive Q
        if (lid == 31) Qe = 0.f;

        if (lid == 0) wtQ[buf][w] = Q;                    // warp total
        __syncthreads();

        // cross-warp Horner over later warps (w2 = 7 .. w+1), Pw in registers
        float4 qa = *reinterpret_cast<const float4*>(&wtQ[buf][0]);
        float4 qb = *reinterpret_cast<const float4*>(&wtQ[buf][4]);
        float Qp = 0.f;
        if (w < 7) Qp = qb.w;
        if (w < 6) Qp = fmaf(pw6, Qp, qb.z);
        if (w < 5) Qp = fmaf(pw5, Qp, qb.y);
        if (w < 4) Qp = fmaf(pw4, Qp, qb.x);
        if (w < 3) Qp = fmaf(pw3, Qp, qa.w);
        if (w < 2) Qp = fmaf(pw2, Qp, qa.z);
        if (w < 1) Qp = fmaf(pw1, Qp, qa.y);

        const float x0  = sx01[buf][0];
        const float xn1 = sx01[buf][1];
        const float seed = fmaf(cN, xn1, -sN * x0);       // prev_{N-1}
        if (t == 0) xv[0] = fmaf(sN, xn1, cN * x0);       // X_0 (fix before replay)

        float prev = fmaf(Pf, seed, fmaf(Pe, Qp, Qe));    // carry entering chunk top

        // ---- replay in place: xv[m] <- out[lo+m+1]; ends with prev = prev_lo ----
#pragma unroll
        for (int m = E - 1; m >= 0; --m) {
            if (lo + m == NN - 1) { xv[m] = 0.f; continue; }
            const float xm = xv[m];
            xv[m] = fmaf(ss[m], xm, cc[m] * prev);
            prev  = fmaf(-ss[m], prev, cc[m] * xm);
        }

        // out[lo]: lanes 1-31 take previous lane's xv[7]; warp heads recompute
        // from the smem-exchanged x[lo-1]; thread 0 has it as prev_0.
        float carry = __shfl_up_sync(0xffffffffu, xv[E - 1], 1);
        if (t == 0)         carry = prev;
        else if (warp_head) carry = fmaf(sprev, sxe[buf][w - 1], cprev * prev);

        float* yr = y + (base + r) * NN;
        float4 o0, o1;
        o0.x = carry; o0.y = xv[0]; o0.z = xv[1]; o0.w = xv[2];
        o1.x = xv[3]; o1.y = xv[4]; o1.z = xv[5]; o1.w = xv[6];
        __stcs(reinterpret_cast<float4*>(yr + lo), o0);
        __stcs(reinterpret_cast<float4*>(yr + lo) + 1, o1);
    }
}

extern "C" void kernel_launch(void* const* d_in, const int* in_sizes, int n_in,
                              void* d_out, int out_size) {
    const float* x   = (const float*)d_in[0];   // (B, N) fp32
    const float* ang = (const float*)d_in[1];   // (N,)  fp32
    float* y = (float*)d_out;                   // (B, N) fp32

    prep_kernel<<<1, T>>>(ang);

    const int rows   = out_size / NN;           // B = 16384
    const int blocks = (rows + R - 1) / R;      // 4096
    givens_kernel<<<blocks, T>>>(x, y, rows);
}

// round 7
// speedup vs baseline: 1.1896x; 1.0711x over previous
#include <cuda_runtime.h>
#include <cstdint>

// Problem constants: x is (16384, 2048) fp32, angles (2048,) fp32, out (16384, 2048) fp32.
constexpr int NN = 2048;   // row length n
constexpr int T  = 256;    // threads per block
constexpr int E  = 8;      // elements per thread (T*E == NN)
constexpr int R  = 4;      // rows per block (processed as 2 pairs)

// Precomputed tables (device globals: no dynamic allocation allowed).
__device__ __align__(16) float g_c[NN];
__device__ __align__(16) float g_s[NN];
// Row-independent scan weights (P-side of the affine scan):
__device__ float g_W5[5][T];   // warp suffix-scan jump weights (prod_{i<d} P_{t+i}, 0 past warp end)
__device__ float g_Pe[T];      // warp-exclusive product (lanes > lid, same warp)
__device__ float g_PfA[T];     // block-exclusive product (threads > t)
__device__ float g_Pw[8];      // per-warp total products

// Fused prep, one block: sincos for all angles + all P-side scan constants,
// computed with log-depth scans (no long serial loops).
__global__ void prep_kernel(const float* __restrict__ ang) {
    __shared__ float Slev[T];
    __shared__ float spw[8];
    const int t = threadIdx.x, lid = t & 31, w = t >> 5, lo = t * E;

    float ssl[E];
#pragma unroll
    for (int m = 0; m < E; ++m) {
        float s, c;
        sincosf(ang[lo + m], &s, &c);
        g_c[lo + m] = c;
        g_s[lo + m] = s;
        ssl[m] = s;
    }

    float P = 1.f;
#pragma unroll
    for (int m = E - 1; m >= 0; --m) {
        if (lo + m == NN - 1) continue;       // k = N-1 is the seed, not a scan step
        P *= -ssl[m];
    }

    // W levels by doubling: S_{2h}[t] = S_h[t] * S_h[t+h]   (0 past warp end)
    float S = P;
    g_W5[0][t] = (lid + 1 < 32) ? S : 0.f;
    for (int di = 1; di < 5; ++di) {
        const int d = 1 << di, half = d >> 1;
        __syncthreads();
        Slev[t] = S;
        __syncthreads();
        float part = (lid + half < 32) ? Slev[t + half] : 0.f;
        S *= part;
        g_W5[di][t] = (lid + d < 32) ? S : 0.f;
    }

    // warp inclusive suffix scan of P (prod over lanes >= lid)
    float Pscan = P;
#pragma unroll
    for (int d = 1; d < 32; d <<= 1) {
        float tmp = __shfl_down_sync(0xffffffffu, Pscan, d);
        if (lid + d < 32) Pscan *= tmp;
    }
    float Pe = __shfl_down_sync(0xffffffffu, Pscan, 1);
    if (lid == 31) Pe = 1.f;
    g_Pe[t] = Pe;
    if (lid == 0) spw[w] = Pscan;             // warp total
    __syncthreads();

    float Pf = Pe;
    for (int w2 = w + 1; w2 < 8; ++w2) Pf *= spw[w2];
    g_PfA[t] = Pf;
    if (t < 8) g_Pw[t] = spw[t];
}

// y_row = G_0 (G_1 (... (G_{N-1} x_row))). First-order affine recurrence on the
// carry; Q-only weighted warp suffix scan (P-side precomputed). Two rows are
// processed per loop iteration: independent scan chains interleave (hiding
// SHFL latency), loads/stores pair up (2x MLP), one barrier serves two rows.
__global__ void __launch_bounds__(T, 4) givens_kernel(const float* __restrict__ x,
                                                      float* __restrict__ y,
                                                      int rows) {
    __shared__ __align__(16) float wtQ[2][2][8];  // [pair parity][row in pair][warp]
    __shared__ float sxe[2][2][8];                // lane-31 x[lo+7] per warp
    __shared__ float sx01[2][2][2];               // x[0], x[N-1]

    const int t   = threadIdx.x;
    const int lid = t & 31;
    const int w   = t >> 5;
    const int lo  = t * E;
    const long base = (long)blockIdx.x * R;
    if (base >= rows) return;

    // ---- per-block constants into registers ----
    float cc[E], ss[E];
    {
        float4 c0 = reinterpret_cast<const float4*>(g_c + lo)[0];
        float4 c1 = reinterpret_cast<const float4*>(g_c + lo)[1];
        cc[0] = c0.x; cc[1] = c0.y; cc[2] = c0.z; cc[3] = c0.w;
        cc[4] = c1.x; cc[5] = c1.y; cc[6] = c1.z; cc[7] = c1.w;
        float4 s0 = reinterpret_cast<const float4*>(g_s + lo)[0];
        float4 s1 = reinterpret_cast<const float4*>(g_s + lo)[1];
        ss[0] = s0.x; ss[1] = s0.y; ss[2] = s0.z; ss[3] = s0.w;
        ss[4] = s1.x; ss[5] = s1.y; ss[6] = s1.z; ss[7] = s1.w;
    }
    float W[5];
#pragma unroll
    for (int di = 0; di < 5; ++di) W[di] = g_W5[di][t];
    const float Pe = g_Pe[t];
    const float Pf = g_PfA[t];
    const float pw1 = g_Pw[1], pw2 = g_Pw[2], pw3 = g_Pw[3],
                pw4 = g_Pw[4], pw5 = g_Pw[5], pw6 = g_Pw[6];
    const float cN = g_c[NN - 1];
    const float sN = g_s[NN - 1];

    // Warp-head lanes (lane 0 of warps 1..7) rebuild out[lo] locally:
    // out[lo] = s[lo-1]*x[lo-1] + c[lo-1]*prev_lo.
    const bool warp_head = (lid == 0) && (w > 0);
    float cprev = 0.f, sprev = 0.f;
    if (warp_head) { cprev = g_c[lo - 1]; sprev = g_s[lo - 1]; }

#pragma unroll 1
    for (int r = 0; r < R; r += 2) {
        if (base + r >= rows) break;
        const bool hasB = (base + r + 1 < rows);
        const int buf = (r >> 1) & 1;
        const float* xrA = x + (base + r) * NN;
        const float* xrB = hasB ? (x + (base + r + 1) * NN) : xrA;

        // ---- loads for both rows (4 LDG.128 in flight) ----
        float xa[E], xb[E];
        {
            float4 a0 = __ldcs(reinterpret_cast<const float4*>(xrA + lo));
            float4 a1 = __ldcs(reinterpret_cast<const float4*>(xrA + lo) + 1);
            float4 b0 = __ldcs(reinterpret_cast<const float4*>(xrB + lo));
            float4 b1 = __ldcs(reinterpret_cast<const float4*>(xrB + lo) + 1);
            xa[0] = a0.x; xa[1] = a0.y; xa[2] = a0.z; xa[3] = a0.w;
            xa[4] = a1.x; xa[5] = a1.y; xa[6] = a1.z; xa[7] = a1.w;
            xb[0] = b0.x; xb[1] = b0.y; xb[2] = b0.z; xb[3] = b0.w;
            xb[4] = b1.x; xb[5] = b1.y; xb[6] = b1.z; xb[7] = b1.w;
        }
        // Boundary exchange through smem (pre-barrier writes):
        if (lid == 31) { sxe[buf][0][w] = xa[7]; sxe[buf][1][w] = xb[7]; }
        if (t == 0)    { sx01[buf][0][0] = xa[0]; sx01[buf][1][0] = xb[0]; }
        if (t == T-1)  { sx01[buf][0][1] = xa[7]; sx01[buf][1][1] = xb[7]; }

        // ---- Q composition for both rows (independent chains) ----
        // Thread 0's Q uses the UNcorrected x[0]; that Q is consumed by nobody.
        float QA = 0.f, QB = 0.f;
#pragma unroll
        for (int m = E - 1; m >= 0; --m) {
            if (lo + m == NN - 1) continue;            // seed step
            QA = fmaf(-ss[m], QA, cc[m] * xa[m]);
            QB = fmaf(-ss[m], QB, cc[m] * xb[m]);
        }

        // ---- Q-only weighted warp suffix scan, both rows interleaved ----
#pragma unroll
        for (int di = 0, d = 1; di < 5; ++di, d <<= 1) {
            float qa2 = __shfl_down_sync(0xffffffffu, QA, d);
            float qb2 = __shfl_down_sync(0xffffffffu, QB, d);
            QA = fmaf(W[di], qa2, QA);
            QB = fmaf(W[di], qb2, QB);
        }
        float QeA = __shfl_down_sync(0xffffffffu, QA, 1);
        float QeB = __shfl_down_sync(0xffffffffu, QB, 1);
        if (lid == 31) { QeA = 0.f; QeB = 0.f; }

        if (lid == 0) { wtQ[buf][0][w] = QA; wtQ[buf][1][w] = QB; }
        __syncthreads();                                // ONE barrier for two rows

        // ---- cross-warp Horner over later warps, both rows ----
        float4 qa0 = *reinterpret_cast<const float4*>(&wtQ[buf][0][0]);
        float4 qa1 = *reinterpret_cast<const float4*>(&wtQ[buf][0][4]);
        float4 qb0 = *reinterpret_cast<const float4*>(&wtQ[buf][1][0]);
        float4 qb1 = *reinterpret_cast<const float4*>(&wtQ[buf][1][4]);
        float QpA = 0.f, QpB = 0.f;
        if (w < 7) { QpA = qa1.w;                 QpB = qb1.w; }
        if (w < 6) { QpA = fmaf(pw6, QpA, qa1.z); QpB = fmaf(pw6, QpB, qb1.z); }
        if (w < 5) { QpA = fmaf(pw5, QpA, qa1.y); QpB = fmaf(pw5, QpB, qb1.y); }
        if (w < 4) { QpA = fmaf(pw4, QpA, qa1.x); QpB = fmaf(pw4, QpB, qb1.x); }
        if (w < 3) { QpA = fmaf(pw3, QpA, qa0.w); QpB = fmaf(pw3, QpB, qb0.w); }
        if (w < 2) { QpA = fmaf(pw2, QpA, qa0.z); QpB = fmaf(pw2, QpB, qb0.z); }
        if (w < 1) { QpA = fmaf(pw1, QpA, qa0.y); QpB = fmaf(pw1, QpB, qb0.y); }

        const float x0A  = sx01[buf][0][0], xn1A = sx01[buf][0][1];
        const float x0B  = sx01[buf][1][0], xn1B = sx01[buf][1][1];
        const float seedA = fmaf(cN, xn1A, -sN * x0A);
        const float seedB = fmaf(cN, xn1B, -sN * x0B);
        if (t == 0) {
            xa[0] = fmaf(sN, xn1A, cN * x0A);          // X_0 fix before replay
            xb[0] = fmaf(sN, xn1B, cN * x0B);
        }

        float prevA = fmaf(Pf, seedA, fmaf(Pe, QpA, QeA));
        float prevB = fmaf(Pf, seedB, fmaf(Pe, QpB, QeB));

        // ---- replay in place, both rows; ends with prev = prev_lo ----
#pragma unroll
        for (int m = E - 1; m >= 0; --m) {
            if (lo + m == NN - 1) { xa[m] = 0.f; xb[m] = 0.f; continue; }
            const float xmA = xa[m], xmB = xb[m];
            xa[m] = fmaf(ss[m], xmA, cc[m] * prevA);
            prevA = fmaf(-ss[m], prevA, cc[m] * xmA);
            xb[m] = fmaf(ss[m], xmB, cc[m] * prevB);
            prevB = fmaf(-ss[m], prevB, cc[m] * xmB);
        }

        // out[lo]: lanes 1-31 take previous lane's xv[7]; warp heads recompute;
        // thread 0 has it as prev_0.
        float carryA = __shfl_up_sync(0xffffffffu, xa[E - 1], 1);
        float carryB = __shfl_up_sync(0xffffffffu, xb[E - 1], 1);
        if (t == 0) {
            carryA = prevA; carryB = prevB;
        } else if (warp_head) {
            carryA = fmaf(sprev, sxe[buf][0][w - 1], cprev * prevA);
            carryB = fmaf(sprev, sxe[buf][1][w - 1], cprev * prevB);
        }

        float* yrA = y + (base + r) * NN;
        float4 oa0, oa1;
        oa0.x = carryA; oa0.y = xa[0]; oa0.z = xa[1]; oa0.w = xa[2];
        oa1.x = xa[3];  oa1.y = xa[4]; oa1.z = xa[5]; oa1.w = xa[6];
        __stcs(reinterpret_cast<float4*>(yrA + lo), oa0);
        __stcs(reinterpret_cast<float4*>(yrA + lo) + 1, oa1);
        if (hasB) {
            float* yrB = y + (base + r + 1) * NN;
            float4 ob0, ob1;
            ob0.x = carryB; ob0.y = xb[0]; ob0.z = xb[1]; ob0.w = xb[2];
            ob1.x = xb[3];  ob1.y = xb[4]; ob1.z = xb[5]; ob1.w = xb[6];
            __stcs(reinterpret_cast<float4*>(yrB + lo), ob0);
            __stcs(reinterpret_cast<float4*>(yrB + lo) + 1, ob1);
        }
    }
}

extern "C" void kernel_launch(void* const* d_in, const int* in_sizes, int n_in,
                              void* d_out, int out_size) {
    const float* x   = (const float*)d_in[0];   // (B, N) fp32
    const float* ang = (const float*)d_in[1];   // (N,)  fp32
    float* y = (float*)d_out;                   // (B, N) fp32

    prep_kernel<<<1, T>>>(ang);

    const int rows   = out_size / NN;           // B = 16384
    const int blocks = (rows + R - 1) / R;      // 4096
    givens_kernel<<<blocks, T>>>(x, y, rows);
}